// round 1
// baseline (speedup 1.0000x reference)
#include <cuda_runtime.h>
#include <math.h>

// Problem-shape constants (padded)
#define NMAX 100352
#define GMAX 512

// Scratch (device globals; allocation-free per harness rules)
__device__ __align__(128) float g_h0[NMAX * 64];     // node features (embed out, then layer outputs, in place)
__device__ __align__(128) float g_xh[NMAX * 64];     // per-layer transformed features
__device__ __align__(128) float g_out[NMAX * 64];    // aggregation accumulator
__device__ __align__(128) float g_als[NMAX * 2];
__device__ __align__(128) float g_ald[NMAX * 2];
__device__ __align__(128) float g_denom[NMAX * 2];
__device__ __align__(128) float g_wself[NMAX * 2];
__device__ __align__(128) float g_bnpart[256 * 128];
__device__ __align__(128) float g_bnstat[128];
__device__ __align__(128) float g_comb[GMAX * 128];

__device__ __forceinline__ float lrelu(float z) { return z > 0.f ? z : 0.2f * z; }

// ---------------- embed: h0 = elu(x @ W_emb + b) ----------------
__global__ void embed_kernel(const float* __restrict__ x, const float* __restrict__ W,
                             const float* __restrict__ b, int N) {
    int t = blockIdx.x * blockDim.x + threadIdx.x;
    int n = t >> 6, c = t & 63;
    if (n >= N) return;
    float4 xv = ((const float4*)x)[n];
    float acc = b[c] + xv.x * W[c] + xv.y * W[64 + c] + xv.z * W[128 + c] + xv.w * W[192 + c];
    g_h0[n * 64 + c] = acc > 0.f ? acc : expm1f(acc);
}

// ---------------- GEMM: g_xh = g_h0 @ W  (N x 64 @ 64 x 64) ----------------
__global__ void gemm_h_kernel(const float* __restrict__ W, int N) {
    __shared__ float As[64 * 64];  // transposed: As[k*64 + r]
    __shared__ float Ws[64 * 64];  // Ws[k*64 + c]
    int row0 = blockIdx.x * 64;
    int tid = threadIdx.x;  // 256

    const float4* W4 = (const float4*)W;
    float4* Ws4 = (float4*)Ws;
#pragma unroll
    for (int i = tid; i < 1024; i += 256) Ws4[i] = W4[i];
#pragma unroll
    for (int i = tid; i < 1024; i += 256) {
        int r = i & 63, kq = i >> 6;
        int n = row0 + r;
        float4 v = (n < N) ? ((const float4*)g_h0)[n * 16 + kq] : make_float4(0.f, 0.f, 0.f, 0.f);
        As[(kq * 4 + 0) * 64 + r] = v.x;
        As[(kq * 4 + 1) * 64 + r] = v.y;
        As[(kq * 4 + 2) * 64 + r] = v.z;
        As[(kq * 4 + 3) * 64 + r] = v.w;
    }
    __syncthreads();

    int c0 = (tid & 15) * 4;
    int r0 = (tid >> 4) * 4;
    float4 acc[4];
#pragma unroll
    for (int i = 0; i < 4; i++) acc[i] = make_float4(0.f, 0.f, 0.f, 0.f);

#pragma unroll
    for (int k = 0; k < 64; k++) {
        float4 av = *(const float4*)&As[k * 64 + r0];
        float4 wv = *(const float4*)&Ws[k * 64 + c0];
        float as_[4] = {av.x, av.y, av.z, av.w};
#pragma unroll
        for (int i = 0; i < 4; i++) {
            acc[i].x += as_[i] * wv.x;
            acc[i].y += as_[i] * wv.y;
            acc[i].z += as_[i] * wv.z;
            acc[i].w += as_[i] * wv.w;
        }
    }
#pragma unroll
    for (int i = 0; i < 4; i++) {
        int n = row0 + r0 + i;
        if (n < N) *(float4*)&g_xh[n * 64 + c0] = acc[i];
    }
}

// ---------------- attention logits per node ----------------
template <int H>
__global__ void attn_kernel(const float* __restrict__ av_s, const float* __restrict__ av_d, int N) {
    int w = (blockIdx.x * blockDim.x + threadIdx.x) >> 5;
    int lane = threadIdx.x & 31;
    if (w >= N) return;
    float x0 = g_xh[w * 64 + lane];
    float x1 = g_xh[w * 64 + 32 + lane];
    float s0 = x0 * av_s[lane], s1 = x1 * av_s[32 + lane];
    float d0 = x0 * av_d[lane], d1 = x1 * av_d[32 + lane];
#pragma unroll
    for (int o = 16; o; o >>= 1) {
        s0 += __shfl_xor_sync(0xffffffffu, s0, o);
        s1 += __shfl_xor_sync(0xffffffffu, s1, o);
        d0 += __shfl_xor_sync(0xffffffffu, d0, o);
        d1 += __shfl_xor_sync(0xffffffffu, d1, o);
    }
    if (lane == 0) {
        if (H == 2) {
            g_als[w * 2] = s0; g_als[w * 2 + 1] = s1;
            g_ald[w * 2] = d0; g_ald[w * 2 + 1] = d1;
        } else {
            g_als[w] = s0 + s1;
            g_ald[w] = d0 + d1;
        }
    }
}

// ---------------- self-loop weight, initializes denom (no memset needed) ----------------
template <int H>
__global__ void self_init_kernel(int N) {
    int n = blockIdx.x * blockDim.x + threadIdx.x;
    if (n >= N) return;
#pragma unroll
    for (int h = 0; h < H; h++) {
        float z = lrelu(g_als[n * H + h] + g_ald[n * H + h]);
        float w = __expf(z);
        g_wself[n * H + h] = w;
        g_denom[n * H + h] = w;
    }
}

// ---------------- pass A: accumulate softmax denominator over real edges ----------------
template <int H>
__global__ void pass_a_kernel(const int* __restrict__ ei, int E) {
    int e = blockIdx.x * blockDim.x + threadIdx.x;
    if (e >= E) return;
    int s = __ldg(&ei[e]);
    int d = __ldg(&ei[E + e]);
#pragma unroll
    for (int h = 0; h < H; h++) {
        float z = lrelu(g_als[s * H + h] + g_ald[d * H + h]);
        atomicAdd(&g_denom[d * H + h], __expf(z));
    }
}

// ---------------- self-loop contribution: plain store, initializes g_out ----------------
template <int H>
__global__ void self_write_kernel(int N) {
    int t = blockIdx.x * blockDim.x + threadIdx.x;
    int n = t >> 6, c = t & 63;
    if (n >= N) return;
    int h = (H == 2) ? (c >> 5) : 0;
    float alpha = g_wself[n * H + h] / (g_denom[n * H + h] + 1e-16f);
    g_out[n * 64 + c] = alpha * g_xh[n * 64 + c];
}

// ---------------- pass B: heavy edge aggregation (4 threads per edge, 16 ch each) ----------
template <int H>
__global__ void pass_b_kernel(const int* __restrict__ ei, int E) {
    int t = blockIdx.x * blockDim.x + threadIdx.x;
    int gid = t >> 2;
    if (gid >= E) return;
    int l = t & 3;
    int s = __ldg(&ei[gid]);
    int d = __ldg(&ei[E + gid]);
    int c0 = l * 16;
    int h = (H == 2) ? (l >> 1) : 0;
    float z = lrelu(g_als[s * H + h] + g_ald[d * H + h]);
    float alpha = __expf(z) / (g_denom[d * H + h] + 1e-16f);
    const float4* src = (const float4*)&g_xh[s * 64 + c0];
    float4* dst = (float4*)&g_out[d * 64 + c0];
#pragma unroll
    for (int j = 0; j < 4; j++) {
        float4 v = src[j];
        atomicAdd(&dst[j], make_float4(alpha * v.x, alpha * v.y, alpha * v.z, alpha * v.w));
    }
}

// ---------------- BN stats: deterministic 2-stage reduction ----------------
__global__ void bn_stats_kernel(const float* __restrict__ bias, int N) {
    int tid = threadIdx.x;
    int c = tid & 63, rq = tid >> 6;
    float bc = bias[c];
    float s = 0.f, s2 = 0.f;
    for (int n = blockIdx.x * 4 + rq; n < N; n += 1024) {
        float v = g_out[n * 64 + c] + bc;
        s += v;
        s2 += v * v;
    }
    __shared__ float sh[512];
    sh[tid] = s;
    sh[256 + tid] = s2;
    __syncthreads();
    if (rq == 0) {
        float ts = sh[c] + sh[64 + c] + sh[128 + c] + sh[192 + c];
        float t2 = sh[256 + c] + sh[256 + 64 + c] + sh[256 + 128 + c] + sh[256 + 192 + c];
        g_bnpart[blockIdx.x * 128 + c] = ts;
        g_bnpart[blockIdx.x * 128 + 64 + c] = t2;
    }
}

__global__ void bn_reduce_kernel() {
    int c = threadIdx.x;  // 128
    float a = 0.f;
    for (int i = 0; i < 256; i++) a += g_bnpart[i * 128 + c];
    g_bnstat[c] = a;
}

__global__ void bn_apply_kernel(const float* __restrict__ bias, const float* __restrict__ gamma,
                                const float* __restrict__ beta, int N) {
    int t = blockIdx.x * blockDim.x + threadIdx.x;
    int n = t >> 6, c = t & 63;
    if (n >= N) return;
    float inv = 1.f / (float)N;
    float mean = g_bnstat[c] * inv;
    float var = g_bnstat[64 + c] * inv - mean * mean;
    float rs = rsqrtf(var + 1e-5f);
    float v = g_out[n * 64 + c] + bias[c];
    float y = gamma[c] * (v - mean) * rs + beta[c];
    g_h0[n * 64 + c] = y > 0.f ? y : expm1f(y);
}

// ---------------- pooling: one block per graph; batch is sorted ----------------
__device__ __forceinline__ int lbound(const int* __restrict__ a, int n, int key) {
    int lo = 0, hi = n;
    while (lo < hi) {
        int mid = (lo + hi) >> 1;
        if (a[mid] < key) lo = mid + 1;
        else hi = mid;
    }
    return lo;
}

__global__ void pool_kernel(const int* __restrict__ batch, int N) {
    int g = blockIdx.x;
    int tid = threadIdx.x;
    int c = tid & 63, rq = tid >> 6;
    int lo = lbound(batch, N, g);
    int hi = lbound(batch, N, g + 1);
    float mx = -INFINITY, sm = 0.f;
    for (int n = lo + rq; n < hi; n += 4) {
        float v = g_h0[n * 64 + c];
        mx = fmaxf(mx, v);
        sm += v;
    }
    __shared__ float shm[256], shs[256];
    shm[tid] = mx;
    shs[tid] = sm;
    __syncthreads();
    if (rq == 0) {
        float m = fmaxf(fmaxf(shm[c], shm[64 + c]), fmaxf(shm[128 + c], shm[192 + c]));
        float s = shs[c] + shs[64 + c] + shs[128 + c] + shs[192 + c];
        int cnt = hi - lo;
        g_comb[g * 128 + c] = cnt > 0 ? m : 0.f;
        g_comb[g * 128 + 64 + c] = s / fmaxf((float)cnt, 1.f);
    }
}

// ---------------- output projection: [G,128] @ [128,128] + b ----------------
__global__ void outproj_kernel(const float* __restrict__ W, const float* __restrict__ b,
                               float* __restrict__ out) {
    int g = blockIdx.x;
    int c = threadIdx.x;  // 128
    __shared__ float row[128];
    row[c] = g_comb[g * 128 + c];
    __syncthreads();
    float acc = b[c];
#pragma unroll 16
    for (int k = 0; k < 128; k++) acc += row[k] * W[k * 128 + c];
    out[g * 128 + c] = acc;
}

// ---------------- host orchestration ----------------
template <int H>
static void run_layer(const int* ei, int E, int N, const float* W, const float* as_,
                      const float* ad_, const float* bias, const float* gamma, const float* beta) {
    gemm_h_kernel<<<(N + 63) / 64, 256>>>(W, N);
    attn_kernel<H><<<(N + 7) / 8, 256>>>(as_, ad_, N);
    self_init_kernel<H><<<(N + 255) / 256, 256>>>(N);
    pass_a_kernel<H><<<(E + 255) / 256, 256>>>(ei, E);
    self_write_kernel<H><<<(N * 64 + 255) / 256, 256>>>(N);
    pass_b_kernel<H><<<(E * 4 + 255) / 256, 256>>>(ei, E);
    bn_stats_kernel<<<256, 256>>>(bias, N);
    bn_reduce_kernel<<<1, 128>>>();
    bn_apply_kernel<<<(N * 64 + 255) / 256, 256>>>(bias, gamma, beta, N);
}

extern "C" void kernel_launch(void* const* d_in, const int* in_sizes, int n_in,
                              void* d_out, int out_size) {
    const float* x     = (const float*)d_in[0];
    const int*   ei    = (const int*)d_in[1];
    const int*   batch = (const int*)d_in[2];
    const float* W_emb = (const float*)d_in[3];
    const float* b_emb = (const float*)d_in[4];
    const float* W1    = (const float*)d_in[5];
    const float* a1s   = (const float*)d_in[6];
    const float* a1d   = (const float*)d_in[7];
    const float* b1    = (const float*)d_in[8];
    const float* g1    = (const float*)d_in[9];
    const float* be1   = (const float*)d_in[10];
    const float* W2    = (const float*)d_in[11];
    const float* a2s   = (const float*)d_in[12];
    const float* a2d   = (const float*)d_in[13];
    const float* b2    = (const float*)d_in[14];
    const float* g2    = (const float*)d_in[15];
    const float* be2   = (const float*)d_in[16];
    const float* Wout  = (const float*)d_in[17];
    const float* bout  = (const float*)d_in[18];

    int N = in_sizes[0] / 4;
    int E = in_sizes[1] / 2;
    int G = out_size / 128;

    embed_kernel<<<(N * 64 + 255) / 256, 256>>>(x, W_emb, b_emb, N);
    run_layer<2>(ei, E, N, W1, a1s, a1d, b1, g1, be1);
    run_layer<1>(ei, E, N, W2, a2s, a2d, b2, g2, be2);
    pool_kernel<<<G, 256>>>(batch, N);
    outproj_kernel<<<G, 128>>>(Wout, bout, (float*)d_out);
}

// round 2
// speedup vs baseline: 1.8740x; 1.8740x over previous
#include <cuda_runtime.h>
#include <math.h>

// Problem-shape constants (padded)
#define NMAX 100352
#define GMAX 512
#define ECAP 3276800

// Scratch (device globals; allocation-free per harness rules)
__device__ __align__(128) float g_h0[NMAX * 64];
__device__ __align__(128) float g_xh[NMAX * 64];
__device__ __align__(128) float g_out[NMAX * 64];
__device__ __align__(128) float g_als[NMAX * 2];
__device__ __align__(128) float g_ald[NMAX * 2];
__device__ __align__(128) float g_bnpart[256 * 128];
__device__ __align__(128) float g_bnstat[128];
__device__ __align__(128) float g_comb[GMAX * 128];
// CSR scratch
__device__ __align__(128) int g_cnt[NMAX];
__device__ __align__(128) int g_cursor[NMAX];
__device__ __align__(128) int g_rowptr[NMAX + 1];
__device__ __align__(128) int g_ecsr[ECAP];
__device__ __align__(128) int g_blocksum[128];

__device__ __forceinline__ float lrelu(float z) { return z > 0.f ? z : 0.2f * z; }

// ---------------- embed: h0 = elu(x @ W_emb + b) ----------------
__global__ void embed_kernel(const float* __restrict__ x, const float* __restrict__ W,
                             const float* __restrict__ b, int N) {
    int t = blockIdx.x * blockDim.x + threadIdx.x;
    int n = t >> 6, c = t & 63;
    if (n >= N) return;
    float4 xv = ((const float4*)x)[n];
    float acc = b[c] + xv.x * W[c] + xv.y * W[64 + c] + xv.z * W[128 + c] + xv.w * W[192 + c];
    g_h0[n * 64 + c] = acc > 0.f ? acc : expm1f(acc);
}

// ---------------- CSR build ----------------
__global__ void hist_zero_kernel(int N) {
    int i = blockIdx.x * blockDim.x + threadIdx.x;
    if (i < N) g_cnt[i] = 0;
}

__global__ void hist_kernel(const int* __restrict__ ei, int E) {
    int e = blockIdx.x * blockDim.x + threadIdx.x;
    if (e >= E) return;
    atomicAdd(&g_cnt[__ldg(&ei[E + e])], 1);
}

// per-block (1024) sums
__global__ void scan_a_kernel(int N) {
    __shared__ int sh[32];
    int i = blockIdx.x * 1024 + threadIdx.x;
    int lane = threadIdx.x & 31, wid = threadIdx.x >> 5;
    int v = (i < N) ? g_cnt[i] : 0;
#pragma unroll
    for (int o = 16; o; o >>= 1) v += __shfl_xor_sync(0xffffffffu, v, o);
    if (lane == 0) sh[wid] = v;
    __syncthreads();
    if (wid == 0) {
        int s = sh[lane];
#pragma unroll
        for (int o = 16; o; o >>= 1) s += __shfl_xor_sync(0xffffffffu, s, o);
        if (lane == 0) g_blocksum[blockIdx.x] = s;
    }
}

// single block scan of <=128 block sums (exclusive), total -> rowptr[N]
__global__ void scan_b_kernel(int NB, int N) {
    __shared__ int sh[128];
    int t = threadIdx.x;
    int v = (t < NB) ? g_blocksum[t] : 0;
    sh[t] = v;
    __syncthreads();
#pragma unroll
    for (int o = 1; o < 128; o <<= 1) {
        int a = (t >= o) ? sh[t - o] : 0;
        __syncthreads();
        sh[t] += a;
        __syncthreads();
    }
    if (t < NB) g_blocksum[t] = sh[t] - v;
    if (t == 127) g_rowptr[N] = sh[127];
}

// per-element exclusive scan within each 1024-block + block offset
__global__ void scan_c_kernel(int N) {
    __shared__ int warpsum[32];
    int i = blockIdx.x * 1024 + threadIdx.x;
    int lane = threadIdx.x & 31, wid = threadIdx.x >> 5;
    int v = (i < N) ? g_cnt[i] : 0;
    int x = v;
#pragma unroll
    for (int o = 1; o < 32; o <<= 1) {
        int y = __shfl_up_sync(0xffffffffu, x, o);
        if (lane >= o) x += y;
    }
    if (lane == 31) warpsum[wid] = x;
    __syncthreads();
    if (wid == 0) {
        int s = warpsum[lane];
#pragma unroll
        for (int o = 1; o < 32; o <<= 1) {
            int y = __shfl_up_sync(0xffffffffu, s, o);
            if (lane >= o) s += y;
        }
        warpsum[lane] = s;
    }
    __syncthreads();
    int woff = (wid > 0) ? warpsum[wid - 1] : 0;
    int excl = x - v + woff + g_blocksum[blockIdx.x];
    if (i < N) {
        g_rowptr[i] = excl;
        g_cursor[i] = excl;
    }
}

__global__ void scatter_kernel(const int* __restrict__ ei, int E) {
    int e = blockIdx.x * blockDim.x + threadIdx.x;
    if (e >= E) return;
    int s = __ldg(&ei[e]);
    int d = __ldg(&ei[E + e]);
    int pos = atomicAdd(&g_cursor[d], 1);
    g_ecsr[pos] = s;
}

// ---------------- GEMM: g_xh = g_h0 @ W  (N x 64 @ 64 x 64) ----------------
__global__ void gemm_h_kernel(const float* __restrict__ W, int N) {
    __shared__ float As[64 * 64];
    __shared__ float Ws[64 * 64];
    int row0 = blockIdx.x * 64;
    int tid = threadIdx.x;  // 256

    const float4* W4 = (const float4*)W;
    float4* Ws4 = (float4*)Ws;
#pragma unroll
    for (int i = tid; i < 1024; i += 256) Ws4[i] = W4[i];
#pragma unroll
    for (int i = tid; i < 1024; i += 256) {
        int r = i & 63, kq = i >> 6;
        int n = row0 + r;
        float4 v = (n < N) ? ((const float4*)g_h0)[n * 16 + kq] : make_float4(0.f, 0.f, 0.f, 0.f);
        As[(kq * 4 + 0) * 64 + r] = v.x;
        As[(kq * 4 + 1) * 64 + r] = v.y;
        As[(kq * 4 + 2) * 64 + r] = v.z;
        As[(kq * 4 + 3) * 64 + r] = v.w;
    }
    __syncthreads();

    int c0 = (tid & 15) * 4;
    int r0 = (tid >> 4) * 4;
    float4 acc[4];
#pragma unroll
    for (int i = 0; i < 4; i++) acc[i] = make_float4(0.f, 0.f, 0.f, 0.f);

#pragma unroll
    for (int k = 0; k < 64; k++) {
        float4 av = *(const float4*)&As[k * 64 + r0];
        float4 wv = *(const float4*)&Ws[k * 64 + c0];
        float as_[4] = {av.x, av.y, av.z, av.w};
#pragma unroll
        for (int i = 0; i < 4; i++) {
            acc[i].x += as_[i] * wv.x;
            acc[i].y += as_[i] * wv.y;
            acc[i].z += as_[i] * wv.z;
            acc[i].w += as_[i] * wv.w;
        }
    }
#pragma unroll
    for (int i = 0; i < 4; i++) {
        int n = row0 + r0 + i;
        if (n < N) *(float4*)&g_xh[n * 64 + c0] = acc[i];
    }
}

// ---------------- attention logits per node ----------------
template <int H>
__global__ void attn_kernel(const float* __restrict__ av_s, const float* __restrict__ av_d, int N) {
    int w = (blockIdx.x * blockDim.x + threadIdx.x) >> 5;
    int lane = threadIdx.x & 31;
    if (w >= N) return;
    float x0 = g_xh[w * 64 + lane];
    float x1 = g_xh[w * 64 + 32 + lane];
    float s0 = x0 * av_s[lane], s1 = x1 * av_s[32 + lane];
    float d0 = x0 * av_d[lane], d1 = x1 * av_d[32 + lane];
#pragma unroll
    for (int o = 16; o; o >>= 1) {
        s0 += __shfl_xor_sync(0xffffffffu, s0, o);
        s1 += __shfl_xor_sync(0xffffffffu, s1, o);
        d0 += __shfl_xor_sync(0xffffffffu, d0, o);
        d1 += __shfl_xor_sync(0xffffffffu, d1, o);
    }
    if (lane == 0) {
        if (H == 2) {
            g_als[w * 2] = s0; g_als[w * 2 + 1] = s1;
            g_ald[w * 2] = d0; g_ald[w * 2 + 1] = d1;
        } else {
            g_als[w] = s0 + s1;
            g_ald[w] = d0 + d1;
        }
    }
}

// ---------------- gather-side aggregation: one warp per destination node ----------------
template <int H>
__global__ void gather_kernel(int N) {
    int d = (blockIdx.x * blockDim.x + threadIdx.x) >> 5;
    int lane = threadIdx.x & 31;
    if (d >= N) return;

    float ald0, ald1, als0, als1;
    if (H == 2) {
        float2 adv = ((const float2*)g_ald)[d];
        float2 asv = ((const float2*)g_als)[d];
        ald0 = adv.x; ald1 = adv.y; als0 = asv.x; als1 = asv.y;
    } else {
        ald0 = ald1 = g_ald[d];
        als0 = als1 = g_als[d];
    }

    // self loop
    float w0 = __expf(lrelu(als0 + ald0));
    float w1 = (H == 2) ? __expf(lrelu(als1 + ald1)) : w0;
    float acc0 = w0 * g_xh[d * 64 + lane];
    float acc1 = w1 * g_xh[d * 64 + 32 + lane];
    float den0 = w0, den1 = w1;

    int p = g_rowptr[d];
    int end = g_rowptr[d + 1];
#pragma unroll 2
    for (; p < end; p++) {
        int s = __ldg(&g_ecsr[p]);
        float e0, e1;
        if (H == 2) {
            float2 av = __ldg(&((const float2*)g_als)[s]);
            e0 = av.x; e1 = av.y;
        } else {
            e0 = e1 = __ldg(&g_als[s]);
        }
        float we0 = __expf(lrelu(e0 + ald0));
        float we1 = (H == 2) ? __expf(lrelu(e1 + ald1)) : we0;
        acc0 += we0 * g_xh[s * 64 + lane];
        acc1 += we1 * g_xh[s * 64 + 32 + lane];
        den0 += we0;
        den1 += we1;
    }
    g_out[d * 64 + lane] = acc0 / (den0 + 1e-16f);
    g_out[d * 64 + 32 + lane] = acc1 / (den1 + 1e-16f);
}

// ---------------- BN stats: deterministic 2-stage reduction ----------------
__global__ void bn_stats_kernel(const float* __restrict__ bias, int N) {
    int tid = threadIdx.x;
    int c = tid & 63, rq = tid >> 6;
    float bc = bias[c];
    float s = 0.f, s2 = 0.f;
    for (int n = blockIdx.x * 4 + rq; n < N; n += 1024) {
        float v = g_out[n * 64 + c] + bc;
        s += v;
        s2 += v * v;
    }
    __shared__ float sh[512];
    sh[tid] = s;
    sh[256 + tid] = s2;
    __syncthreads();
    if (rq == 0) {
        float ts = sh[c] + sh[64 + c] + sh[128 + c] + sh[192 + c];
        float t2 = sh[256 + c] + sh[256 + 64 + c] + sh[256 + 128 + c] + sh[256 + 192 + c];
        g_bnpart[blockIdx.x * 128 + c] = ts;
        g_bnpart[blockIdx.x * 128 + 64 + c] = t2;
    }
}

__global__ void bn_reduce_kernel() {
    int c = threadIdx.x;  // 128
    float a = 0.f;
    for (int i = 0; i < 256; i++) a += g_bnpart[i * 128 + c];
    g_bnstat[c] = a;
}

__global__ void bn_apply_kernel(const float* __restrict__ bias, const float* __restrict__ gamma,
                                const float* __restrict__ beta, int N) {
    int t = blockIdx.x * blockDim.x + threadIdx.x;
    int n = t >> 6, c = t & 63;
    if (n >= N) return;
    float inv = 1.f / (float)N;
    float mean = g_bnstat[c] * inv;
    float var = g_bnstat[64 + c] * inv - mean * mean;
    float rs = rsqrtf(var + 1e-5f);
    float v = g_out[n * 64 + c] + bias[c];
    float y = gamma[c] * (v - mean) * rs + beta[c];
    g_h0[n * 64 + c] = y > 0.f ? y : expm1f(y);
}

// ---------------- pooling: one block per graph; batch is sorted ----------------
__device__ __forceinline__ int lbound(const int* __restrict__ a, int n, int key) {
    int lo = 0, hi = n;
    while (lo < hi) {
        int mid = (lo + hi) >> 1;
        if (a[mid] < key) lo = mid + 1;
        else hi = mid;
    }
    return lo;
}

__global__ void pool_kernel(const int* __restrict__ batch, int N) {
    int g = blockIdx.x;
    int tid = threadIdx.x;
    int c = tid & 63, rq = tid >> 6;
    int lo = lbound(batch, N, g);
    int hi = lbound(batch, N, g + 1);
    float mx = -INFINITY, sm = 0.f;
    for (int n = lo + rq; n < hi; n += 4) {
        float v = g_h0[n * 64 + c];
        mx = fmaxf(mx, v);
        sm += v;
    }
    __shared__ float shm[256], shs[256];
    shm[tid] = mx;
    shs[tid] = sm;
    __syncthreads();
    if (rq == 0) {
        float m = fmaxf(fmaxf(shm[c], shm[64 + c]), fmaxf(shm[128 + c], shm[192 + c]));
        float s = shs[c] + shs[64 + c] + shs[128 + c] + shs[192 + c];
        int cnt = hi - lo;
        g_comb[g * 128 + c] = cnt > 0 ? m : 0.f;
        g_comb[g * 128 + 64 + c] = s / fmaxf((float)cnt, 1.f);
    }
}

// ---------------- output projection: [G,128] @ [128,128] + b ----------------
__global__ void outproj_kernel(const float* __restrict__ W, const float* __restrict__ b,
                               float* __restrict__ out) {
    int g = blockIdx.x;
    int c = threadIdx.x;  // 128
    __shared__ float row[128];
    row[c] = g_comb[g * 128 + c];
    __syncthreads();
    float acc = b[c];
#pragma unroll 16
    for (int k = 0; k < 128; k++) acc += row[k] * W[k * 128 + c];
    out[g * 128 + c] = acc;
}

// ---------------- host orchestration ----------------
template <int H>
static void run_layer(int E, int N, const float* W, const float* as_,
                      const float* ad_, const float* bias, const float* gamma, const float* beta) {
    gemm_h_kernel<<<(N + 63) / 64, 256>>>(W, N);
    attn_kernel<H><<<(N + 7) / 8, 256>>>(as_, ad_, N);
    gather_kernel<H><<<(N * 32 + 255) / 256, 256>>>(N);
    bn_stats_kernel<<<256, 256>>>(bias, N);
    bn_reduce_kernel<<<1, 128>>>();
    bn_apply_kernel<<<(N * 64 + 255) / 256, 256>>>(bias, gamma, beta, N);
}

extern "C" void kernel_launch(void* const* d_in, const int* in_sizes, int n_in,
                              void* d_out, int out_size) {
    const float* x     = (const float*)d_in[0];
    const int*   ei    = (const int*)d_in[1];
    const int*   batch = (const int*)d_in[2];
    const float* W_emb = (const float*)d_in[3];
    const float* b_emb = (const float*)d_in[4];
    const float* W1    = (const float*)d_in[5];
    const float* a1s   = (const float*)d_in[6];
    const float* a1d   = (const float*)d_in[7];
    const float* b1    = (const float*)d_in[8];
    const float* g1    = (const float*)d_in[9];
    const float* be1   = (const float*)d_in[10];
    const float* W2    = (const float*)d_in[11];
    const float* a2s   = (const float*)d_in[12];
    const float* a2d   = (const float*)d_in[13];
    const float* b2    = (const float*)d_in[14];
    const float* g2    = (const float*)d_in[15];
    const float* be2   = (const float*)d_in[16];
    const float* Wout  = (const float*)d_in[17];
    const float* bout  = (const float*)d_in[18];

    int N = in_sizes[0] / 4;
    int E = in_sizes[1] / 2;
    int G = out_size / 128;
    int NB = (N + 1023) / 1024;

    // CSR build (once per call; reused by both layers)
    hist_zero_kernel<<<(N + 255) / 256, 256>>>(N);
    hist_kernel<<<(E + 255) / 256, 256>>>(ei, E);
    scan_a_kernel<<<NB, 1024>>>(N);
    scan_b_kernel<<<1, 128>>>(NB, N);
    scan_c_kernel<<<NB, 1024>>>(N);
    scatter_kernel<<<(E + 255) / 256, 256>>>(ei, E);

    embed_kernel<<<(N * 64 + 255) / 256, 256>>>(x, W_emb, b_emb, N);
    run_layer<2>(E, N, W1, a1s, a1d, b1, g1, be1);
    run_layer<1>(E, N, W2, a2s, a2d, b2, g2, be2);
    pool_kernel<<<G, 256>>>(batch, N);
    outproj_kernel<<<G, 128>>>(Wout, bout, (float*)d_out);
}

// round 3
// speedup vs baseline: 2.1139x; 1.1280x over previous
#include <cuda_runtime.h>
#include <cuda_fp16.h>
#include <math.h>

// Problem-shape constants (padded)
#define NMAX 100352
#define GMAX 512
#define ECAP 3276800

// Scratch (device globals; allocation-free per harness rules)
__device__ __align__(128) float g_h0[NMAX * 64];      // embed output (fp32)
__device__ __align__(128) __half g_xh16[NMAX * 64];   // transformed features (fp16)
__device__ __align__(128) float g_out[NMAX * 64];     // raw aggregation output (pre-bias, pre-BN)
__device__ __align__(128) float g_als[NMAX * 2];
__device__ __align__(128) float g_ald[NMAX * 2];
__device__ __align__(128) float g_bnpart1[32 * 128];
__device__ __align__(128) float g_bnpart2[32 * 128];
__device__ __align__(128) float g_bnstat1[128];
__device__ __align__(128) float g_bnstat2[128];
__device__ __align__(128) float g_comb[GMAX * 128];
// CSR scratch
__device__ __align__(128) int g_cnt[NMAX];
__device__ __align__(128) int g_cursor[NMAX];
__device__ __align__(128) int g_rowptr[NMAX + 1];
__device__ __align__(128) int g_ecsr[ECAP];
__device__ __align__(128) int g_blocksum[128];

__device__ __forceinline__ float lrelu(float z) { return z > 0.f ? z : 0.2f * z; }
__device__ __forceinline__ float elu(float z) { return z > 0.f ? z : expm1f(z); }

// ---------------- embed: h0 = elu(x @ W_emb + b); also zero CSR cnt + bn partials ----------
__global__ void embed_kernel(const float* __restrict__ x, const float* __restrict__ W,
                             const float* __restrict__ b, int N) {
    int t = blockIdx.x * blockDim.x + threadIdx.x;
    if (t < 4096) { g_bnpart1[t] = 0.f; g_bnpart2[t] = 0.f; }
    int n = t >> 6, c = t & 63;
    if (n >= N) return;
    float4 xv = ((const float4*)x)[n];
    float acc = b[c] + xv.x * W[c] + xv.y * W[64 + c] + xv.z * W[128 + c] + xv.w * W[192 + c];
    g_h0[n * 64 + c] = elu(acc);
}

// ---------------- CSR build ----------------
__global__ void hist_zero_kernel(int N) {
    int i = blockIdx.x * blockDim.x + threadIdx.x;
    if (i < N) g_cnt[i] = 0;
}

__global__ void hist_kernel(const int* __restrict__ ei, int E) {
    int e = blockIdx.x * blockDim.x + threadIdx.x;
    if (e >= E) return;
    atomicAdd(&g_cnt[__ldg(&ei[E + e])], 1);
}

__global__ void scan_a_kernel(int N) {
    __shared__ int sh[32];
    int i = blockIdx.x * 1024 + threadIdx.x;
    int lane = threadIdx.x & 31, wid = threadIdx.x >> 5;
    int v = (i < N) ? g_cnt[i] : 0;
#pragma unroll
    for (int o = 16; o; o >>= 1) v += __shfl_xor_sync(0xffffffffu, v, o);
    if (lane == 0) sh[wid] = v;
    __syncthreads();
    if (wid == 0) {
        int s = sh[lane];
#pragma unroll
        for (int o = 16; o; o >>= 1) s += __shfl_xor_sync(0xffffffffu, s, o);
        if (lane == 0) g_blocksum[blockIdx.x] = s;
    }
}

__global__ void scan_b_kernel(int NB, int N) {
    __shared__ int sh[128];
    int t = threadIdx.x;
    int v = (t < NB) ? g_blocksum[t] : 0;
    sh[t] = v;
    __syncthreads();
#pragma unroll
    for (int o = 1; o < 128; o <<= 1) {
        int a = (t >= o) ? sh[t - o] : 0;
        __syncthreads();
        sh[t] += a;
        __syncthreads();
    }
    if (t < NB) g_blocksum[t] = sh[t] - v;
    if (t == 127) g_rowptr[N] = sh[127];
}

__global__ void scan_c_kernel(int N) {
    __shared__ int warpsum[32];
    int i = blockIdx.x * 1024 + threadIdx.x;
    int lane = threadIdx.x & 31, wid = threadIdx.x >> 5;
    int v = (i < N) ? g_cnt[i] : 0;
    int x = v;
#pragma unroll
    for (int o = 1; o < 32; o <<= 1) {
        int y = __shfl_up_sync(0xffffffffu, x, o);
        if (lane >= o) x += y;
    }
    if (lane == 31) warpsum[wid] = x;
    __syncthreads();
    if (wid == 0) {
        int s = warpsum[lane];
#pragma unroll
        for (int o = 1; o < 32; o <<= 1) {
            int y = __shfl_up_sync(0xffffffffu, s, o);
            if (lane >= o) s += y;
        }
        warpsum[lane] = s;
    }
    __syncthreads();
    int woff = (wid > 0) ? warpsum[wid - 1] : 0;
    int excl = x - v + woff + g_blocksum[blockIdx.x];
    if (i < N) {
        g_rowptr[i] = excl;
        g_cursor[i] = excl;
    }
}

__global__ void scatter_kernel(const int* __restrict__ ei, int E) {
    int e = blockIdx.x * blockDim.x + threadIdx.x;
    if (e >= E) return;
    int s = __ldg(&ei[e]);
    int d = __ldg(&ei[E + e]);
    int pos = atomicAdd(&g_cursor[d], 1);
    g_ecsr[pos] = s;
}

// ---------------- fused GEMM: xh16 = (BN?elu(BN(src)):src) @ W, + attention logits ----------
// src is g_h0 (layer 1, BN=false) or g_out (layer 2, BN=true with layer-1 params).
template <int H, bool BN>
__global__ void gemm_fused_kernel(const float* __restrict__ W,
                                  const float* __restrict__ a_src, const float* __restrict__ a_dst,
                                  const float* __restrict__ src,
                                  const float* __restrict__ bias_prev,
                                  const float* __restrict__ gamma, const float* __restrict__ beta,
                                  const float* __restrict__ stat, int N) {
    __shared__ float As[64 * 64];   // As[k*64 + r]
    __shared__ float Ws[64 * 64];   // Ws[k*64 + c]
    __shared__ float shS[64][16];
    __shared__ float shD[64][16];
    __shared__ float s_sc[64], s_off[64];

    int row0 = blockIdx.x * 64;
    int tid = threadIdx.x;  // 256

    if (BN) {
        if (tid < 64) {
            float invN = 1.f / (float)N;
            float mean = stat[tid] * invN;
            float var = stat[64 + tid] * invN - mean * mean;
            float scv = gamma[tid] * rsqrtf(var + 1e-5f);
            s_sc[tid] = scv;
            s_off[tid] = (bias_prev[tid] - mean) * scv + beta[tid];
        }
        __syncthreads();
    }

    const float4* W4 = (const float4*)W;
    float4* Ws4 = (float4*)Ws;
#pragma unroll
    for (int i = tid; i < 1024; i += 256) Ws4[i] = W4[i];
#pragma unroll
    for (int i = tid; i < 1024; i += 256) {
        int r = i & 63, kq = i >> 6;
        int n = row0 + r;
        float4 v = make_float4(0.f, 0.f, 0.f, 0.f);
        if (n < N) {
            v = ((const float4*)src)[n * 16 + kq];
            if (BN) {
                int c = kq * 4;
                v.x = elu(v.x * s_sc[c + 0] + s_off[c + 0]);
                v.y = elu(v.y * s_sc[c + 1] + s_off[c + 1]);
                v.z = elu(v.z * s_sc[c + 2] + s_off[c + 2]);
                v.w = elu(v.w * s_sc[c + 3] + s_off[c + 3]);
            }
        }
        As[(kq * 4 + 0) * 64 + r] = v.x;
        As[(kq * 4 + 1) * 64 + r] = v.y;
        As[(kq * 4 + 2) * 64 + r] = v.z;
        As[(kq * 4 + 3) * 64 + r] = v.w;
    }
    __syncthreads();

    int c0 = (tid & 15) * 4;
    int r0 = (tid >> 4) * 4;
    float4 acc[4];
#pragma unroll
    for (int i = 0; i < 4; i++) acc[i] = make_float4(0.f, 0.f, 0.f, 0.f);

#pragma unroll
    for (int k = 0; k < 64; k++) {
        float4 av = *(const float4*)&As[k * 64 + r0];
        float4 wv = *(const float4*)&Ws[k * 64 + c0];
        float as_[4] = {av.x, av.y, av.z, av.w};
#pragma unroll
        for (int i = 0; i < 4; i++) {
            acc[i].x += as_[i] * wv.x;
            acc[i].y += as_[i] * wv.y;
            acc[i].z += as_[i] * wv.z;
            acc[i].w += as_[i] * wv.w;
        }
    }

    // store fp16 features + attention logit partials
    float a_s0 = a_src[c0], a_s1 = a_src[c0 + 1], a_s2 = a_src[c0 + 2], a_s3 = a_src[c0 + 3];
    float a_d0 = a_dst[c0], a_d1 = a_dst[c0 + 1], a_d2 = a_dst[c0 + 2], a_d3 = a_dst[c0 + 3];
    int cg = tid & 15;
#pragma unroll
    for (int i = 0; i < 4; i++) {
        int r = r0 + i;
        int n = row0 + r;
        if (n < N) {
            __half2 h01 = __floats2half2_rn(acc[i].x, acc[i].y);
            __half2 h23 = __floats2half2_rn(acc[i].z, acc[i].w);
            uint2 pack;
            pack.x = *(unsigned int*)&h01;
            pack.y = *(unsigned int*)&h23;
            *(uint2*)&g_xh16[n * 64 + c0] = pack;
        }
        shS[r][cg] = acc[i].x * a_s0 + acc[i].y * a_s1 + acc[i].z * a_s2 + acc[i].w * a_s3;
        shD[r][cg] = acc[i].x * a_d0 + acc[i].y * a_d1 + acc[i].z * a_d2 + acc[i].w * a_d3;
    }
    __syncthreads();

    if (tid < 128) {
        int row = tid >> 1, sel = tid & 1;
        int n = row0 + row;
        if (n < N) {
            const float* arr = sel ? &shD[row][0] : &shS[row][0];
            float* dsta = sel ? g_ald : g_als;
            if (H == 2) {
                float h0 = 0.f, h1 = 0.f;
#pragma unroll
                for (int j = 0; j < 8; j++) { h0 += arr[j]; h1 += arr[8 + j]; }
                dsta[2 * n] = h0;
                dsta[2 * n + 1] = h1;
            } else {
                float t = 0.f;
#pragma unroll
                for (int j = 0; j < 16; j++) t += arr[j];
                dsta[n] = t;
            }
        }
    }
}

// ---------------- gather: one warp per destination node, fp16 features, fused BN stats ------
template <int H>
__global__ void gather_kernel(const float* __restrict__ bias, float* __restrict__ bnpart, int N) {
    __shared__ float2 shS[8][32];
    __shared__ float2 shQ[8][32];
    int w = threadIdx.x >> 5, lane = threadIdx.x & 31;
    int d = blockIdx.x * 8 + w;
    bool valid = (d < N);
    float2 outv = make_float2(0.f, 0.f);

    if (valid) {
        float ald0, ald1, als0, als1;
        if (H == 2) {
            float2 adv = ((const float2*)g_ald)[d];
            float2 asv = ((const float2*)g_als)[d];
            ald0 = adv.x; ald1 = adv.y; als0 = asv.x; als1 = asv.y;
        } else {
            ald0 = ald1 = g_ald[d];
            als0 = als1 = g_als[d];
        }
        bool hi = (H == 2) && (lane >= 16);
        float ald_own = hi ? ald1 : ald0;
        float wself = __expf(lrelu((hi ? als1 : als0) + ald_own));

        float2 fv = __half22float2(((const __half2*)g_xh16)[d * 32 + lane]);
        float accx = wself * fv.x, accy = wself * fv.y, den = wself;

        int p = g_rowptr[d];
        int end = g_rowptr[d + 1];
        int s_next = (p < end) ? __ldg(&g_ecsr[p]) : 0;
        for (; p < end; p++) {
            int s = s_next;
            if (p + 1 < end) s_next = __ldg(&g_ecsr[p + 1]);
            float e;
            if (H == 2) {
                float2 av = __ldg(&((const float2*)g_als)[s]);
                e = hi ? av.y : av.x;
            } else {
                e = __ldg(&g_als[s]);
            }
            float we = __expf(lrelu(e + ald_own));
            float2 nf = __half22float2(__ldg(&((const __half2*)g_xh16)[s * 32 + lane]));
            accx += we * nf.x;
            accy += we * nf.y;
            den += we;
        }
        float inv = 1.f / (den + 1e-16f);
        outv = make_float2(accx * inv, accy * inv);
        ((float2*)g_out)[d * 32 + lane] = outv;
    }

    // fused BN statistics: v = out + bias
    float2 bv = ((const float2*)bias)[lane];
    float vx = valid ? outv.x + bv.x : 0.f;
    float vy = valid ? outv.y + bv.y : 0.f;
    shS[w][lane] = make_float2(vx, vy);
    shQ[w][lane] = make_float2(vx * vx, vy * vy);
    __syncthreads();

    int c = threadIdx.x;
    if (c < 64) {
        int l = c >> 1, comp = c & 1;
        float s = 0.f, q = 0.f;
#pragma unroll
        for (int i = 0; i < 8; i++) {
            float2 sv = shS[i][l];
            float2 qv = shQ[i][l];
            s += comp ? sv.y : sv.x;
            q += comp ? qv.y : qv.x;
        }
        float* base = bnpart + (blockIdx.x & 31) * 128;
        atomicAdd(base + c, s);
        atomicAdd(base + 64 + c, q);
    }
}

__global__ void bn_finalize_kernel(const float* __restrict__ part, float* __restrict__ stat) {
    int c = threadIdx.x;  // 128
    float a = 0.f;
#pragma unroll
    for (int i = 0; i < 32; i++) a += part[i * 128 + c];
    stat[c] = a;
}

// ---------------- pooling with inline BN2+ELU: one block per graph; batch sorted ------------
__device__ __forceinline__ int lbound(const int* __restrict__ a, int n, int key) {
    int lo = 0, hi = n;
    while (lo < hi) {
        int mid = (lo + hi) >> 1;
        if (a[mid] < key) lo = mid + 1;
        else hi = mid;
    }
    return lo;
}

__global__ void pool_kernel(const int* __restrict__ batch,
                            const float* __restrict__ bias, const float* __restrict__ gamma,
                            const float* __restrict__ beta, const float* __restrict__ stat,
                            int N) {
    __shared__ float s_sc[64], s_off[64];
    __shared__ float shm[256], shs[256];
    int tid = threadIdx.x;
    if (tid < 64) {
        float invN = 1.f / (float)N;
        float mean = stat[tid] * invN;
        float var = stat[64 + tid] * invN - mean * mean;
        float scv = gamma[tid] * rsqrtf(var + 1e-5f);
        s_sc[tid] = scv;
        s_off[tid] = (bias[tid] - mean) * scv + beta[tid];
    }
    __syncthreads();

    int g = blockIdx.x;
    int c = tid & 63, rq = tid >> 6;
    int lo = lbound(batch, N, g);
    int hi = lbound(batch, N, g + 1);
    float sc = s_sc[c], off = s_off[c];
    float mx = -INFINITY, sm = 0.f;
    for (int n = lo + rq; n < hi; n += 4) {
        float v = elu(g_out[n * 64 + c] * sc + off);
        mx = fmaxf(mx, v);
        sm += v;
    }
    shm[tid] = mx;
    shs[tid] = sm;
    __syncthreads();
    if (rq == 0) {
        float m = fmaxf(fmaxf(shm[c], shm[64 + c]), fmaxf(shm[128 + c], shm[192 + c]));
        float s = shs[c] + shs[64 + c] + shs[128 + c] + shs[192 + c];
        int cnt = hi - lo;
        g_comb[g * 128 + c] = cnt > 0 ? m : 0.f;
        g_comb[g * 128 + 64 + c] = s / fmaxf((float)cnt, 1.f);
    }
}

// ---------------- output projection: [G,128] @ [128,128] + b ----------------
__global__ void outproj_kernel(const float* __restrict__ W, const float* __restrict__ b,
                               float* __restrict__ out) {
    int g = blockIdx.x;
    int c = threadIdx.x;  // 128
    __shared__ float row[128];
    row[c] = g_comb[g * 128 + c];
    __syncthreads();
    float acc = b[c];
#pragma unroll 16
    for (int k = 0; k < 128; k++) acc += row[k] * W[k * 128 + c];
    out[g * 128 + c] = acc;
}

// ---------------- host orchestration ----------------
extern "C" void kernel_launch(void* const* d_in, const int* in_sizes, int n_in,
                              void* d_out, int out_size) {
    const float* x     = (const float*)d_in[0];
    const int*   ei    = (const int*)d_in[1];
    const int*   batch = (const int*)d_in[2];
    const float* W_emb = (const float*)d_in[3];
    const float* b_emb = (const float*)d_in[4];
    const float* W1    = (const float*)d_in[5];
    const float* a1s   = (const float*)d_in[6];
    const float* a1d   = (const float*)d_in[7];
    const float* b1    = (const float*)d_in[8];
    const float* g1    = (const float*)d_in[9];
    const float* be1   = (const float*)d_in[10];
    const float* W2    = (const float*)d_in[11];
    const float* a2s   = (const float*)d_in[12];
    const float* a2d   = (const float*)d_in[13];
    const float* b2    = (const float*)d_in[14];
    const float* g2    = (const float*)d_in[15];
    const float* be2   = (const float*)d_in[16];
    const float* Wout  = (const float*)d_in[17];
    const float* bout  = (const float*)d_in[18];

    int N = in_sizes[0] / 4;
    int E = in_sizes[1] / 2;
    int G = out_size / 128;
    int NB = (N + 1023) / 1024;

    // device-global pointers usable from host code via symbol (same address space on device)
    float* p_h0;   cudaGetSymbolAddress((void**)&p_h0, g_h0);
    float* p_out;  cudaGetSymbolAddress((void**)&p_out, g_out);
    float* p_bp1;  cudaGetSymbolAddress((void**)&p_bp1, g_bnpart1);
    float* p_bp2;  cudaGetSymbolAddress((void**)&p_bp2, g_bnpart2);
    float* p_st1;  cudaGetSymbolAddress((void**)&p_st1, g_bnstat1);
    float* p_st2;  cudaGetSymbolAddress((void**)&p_st2, g_bnstat2);

    // CSR build (reused by both layers)
    hist_zero_kernel<<<(N + 255) / 256, 256>>>(N);
    hist_kernel<<<(E + 255) / 256, 256>>>(ei, E);
    scan_a_kernel<<<NB, 1024>>>(N);
    scan_b_kernel<<<1, 128>>>(NB, N);
    scan_c_kernel<<<NB, 1024>>>(N);
    scatter_kernel<<<(E + 255) / 256, 256>>>(ei, E);

    embed_kernel<<<(N * 64 + 255) / 256, 256>>>(x, W_emb, b_emb, N);

    // layer 1
    gemm_fused_kernel<2, false><<<(N + 63) / 64, 256>>>(W1, a1s, a1d, p_h0,
                                                        nullptr, nullptr, nullptr, nullptr, N);
    gather_kernel<2><<<(N + 7) / 8, 256>>>(b1, p_bp1, N);
    bn_finalize_kernel<<<1, 128>>>(p_bp1, p_st1);

    // layer 2 (BN1+ELU applied on load of g_out)
    gemm_fused_kernel<1, true><<<(N + 63) / 64, 256>>>(W2, a2s, a2d, p_out,
                                                       b1, g1, be1, p_st1, N);
    gather_kernel<1><<<(N + 7) / 8, 256>>>(b2, p_bp2, N);
    bn_finalize_kernel<<<1, 128>>>(p_bp2, p_st2);

    // pool (BN2+ELU applied on load) + projection
    pool_kernel<<<G, 256>>>(batch, b2, g2, be2, p_st2, N);
    outproj_kernel<<<G, 128>>>(Wout, bout, (float*)d_out);
}

// round 4
// speedup vs baseline: 2.1570x; 1.0204x over previous
#include <cuda_runtime.h>
#include <cuda_fp16.h>
#include <math.h>

// Problem-shape constants (padded)
#define NMAX 100352
#define GMAX 512
#define ECAP 3276800

// Scratch (device globals; allocation-free per harness rules)
__device__ __align__(128) float g_h0[NMAX * 64];      // embed output (fp32)
__device__ __align__(128) __half g_xh16[NMAX * 64];   // transformed features (fp16)
__device__ __align__(128) float g_out[NMAX * 64];     // raw aggregation output (pre-bias, pre-BN)
__device__ __align__(128) float g_als[NMAX * 2];
__device__ __align__(128) float g_ald[NMAX * 2];
__device__ __align__(128) float g_bnpart1[32 * 128];
__device__ __align__(128) float g_bnpart2[32 * 128];
__device__ __align__(128) float g_bnstat1[128];
__device__ __align__(128) float g_bnstat2[128];
__device__ __align__(128) float g_comb[GMAX * 128];
// CSR scratch
__device__ __align__(128) int g_cnt[NMAX];
__device__ __align__(128) int g_cursor[NMAX];
__device__ __align__(128) int g_rowptr[NMAX + 1];
__device__ __align__(128) int g_ecsr[ECAP];
__device__ __align__(128) int g_blocksum[128];

__device__ __forceinline__ float lrelu(float z) { return z > 0.f ? z : 0.2f * z; }
__device__ __forceinline__ float elu(float z) { return z > 0.f ? z : expm1f(z); }

// ---------------- CSR build ----------------
__global__ void hist_zero_kernel(int N) {
    int i = blockIdx.x * blockDim.x + threadIdx.x;
    if (i < 4096) { g_bnpart1[i] = 0.f; g_bnpart2[i] = 0.f; }
    if (i < N) g_cnt[i] = 0;
}

__global__ void hist_kernel(const int* __restrict__ ei, int E) {
    int e = blockIdx.x * blockDim.x + threadIdx.x;
    if (e >= E) return;
    atomicAdd(&g_cnt[__ldg(&ei[E + e])], 1);
}

__global__ void scan_a_kernel(int N) {
    __shared__ int sh[32];
    int i = blockIdx.x * 1024 + threadIdx.x;
    int lane = threadIdx.x & 31, wid = threadIdx.x >> 5;
    int v = (i < N) ? g_cnt[i] : 0;
#pragma unroll
    for (int o = 16; o; o >>= 1) v += __shfl_xor_sync(0xffffffffu, v, o);
    if (lane == 0) sh[wid] = v;
    __syncthreads();
    if (wid == 0) {
        int s = sh[lane];
#pragma unroll
        for (int o = 16; o; o >>= 1) s += __shfl_xor_sync(0xffffffffu, s, o);
        if (lane == 0) g_blocksum[blockIdx.x] = s;
    }
}

__global__ void scan_b_kernel(int NB, int N) {
    __shared__ int sh[128];
    int t = threadIdx.x;
    int v = (t < NB) ? g_blocksum[t] : 0;
    sh[t] = v;
    __syncthreads();
#pragma unroll
    for (int o = 1; o < 128; o <<= 1) {
        int a = (t >= o) ? sh[t - o] : 0;
        __syncthreads();
        sh[t] += a;
        __syncthreads();
    }
    if (t < NB) g_blocksum[t] = sh[t] - v;
    if (t == 127) g_rowptr[N] = sh[127];
}

__global__ void scan_c_kernel(int N) {
    __shared__ int warpsum[32];
    int i = blockIdx.x * 1024 + threadIdx.x;
    int lane = threadIdx.x & 31, wid = threadIdx.x >> 5;
    int v = (i < N) ? g_cnt[i] : 0;
    int x = v;
#pragma unroll
    for (int o = 1; o < 32; o <<= 1) {
        int y = __shfl_up_sync(0xffffffffu, x, o);
        if (lane >= o) x += y;
    }
    if (lane == 31) warpsum[wid] = x;
    __syncthreads();
    if (wid == 0) {
        int s = warpsum[lane];
#pragma unroll
        for (int o = 1; o < 32; o <<= 1) {
            int y = __shfl_up_sync(0xffffffffu, s, o);
            if (lane >= o) s += y;
        }
        warpsum[lane] = s;
    }
    __syncthreads();
    int woff = (wid > 0) ? warpsum[wid - 1] : 0;
    int excl = x - v + woff + g_blocksum[blockIdx.x];
    if (i < N) {
        g_rowptr[i] = excl;
        g_cursor[i] = excl;
    }
}

__global__ void scatter_kernel(const int* __restrict__ ei, int E) {
    int e = blockIdx.x * blockDim.x + threadIdx.x;
    if (e >= E) return;
    int s = __ldg(&ei[e]);
    int d = __ldg(&ei[E + e]);
    int pos = atomicAdd(&g_cursor[d], 1);
    g_ecsr[pos] = s;
}

// ---------------- embed: h0 = elu(x @ W_emb + b) ----------------
__global__ void embed_kernel(const float* __restrict__ x, const float* __restrict__ W,
                             const float* __restrict__ b, int N) {
    int t = blockIdx.x * blockDim.x + threadIdx.x;
    int n = t >> 6, c = t & 63;
    if (n >= N) return;
    float4 xv = ((const float4*)x)[n];
    float acc = b[c] + xv.x * W[c] + xv.y * W[64 + c] + xv.z * W[128 + c] + xv.w * W[192 + c];
    g_h0[n * 64 + c] = elu(acc);
}

// ---------------- fused GEMM: xh16 = (BN?elu(BN(src)):src) @ W, + attention logits ----------
template <int H, bool BN>
__global__ void gemm_fused_kernel(const float* __restrict__ W,
                                  const float* __restrict__ a_src, const float* __restrict__ a_dst,
                                  const float* __restrict__ src,
                                  const float* __restrict__ bias_prev,
                                  const float* __restrict__ gamma, const float* __restrict__ beta,
                                  const float* __restrict__ stat, int N) {
    __shared__ float As[64 * 64];   // As[k*64 + r]
    __shared__ float Ws[64 * 64];   // Ws[k*64 + c]
    __shared__ float shS[64][16];
    __shared__ float shD[64][16];
    __shared__ float s_sc[64], s_off[64];

    int row0 = blockIdx.x * 64;
    int tid = threadIdx.x;  // 256

    if (BN) {
        if (tid < 64) {
            float invN = 1.f / (float)N;
            float mean = stat[tid] * invN;
            float var = stat[64 + tid] * invN - mean * mean;
            float scv = gamma[tid] * rsqrtf(var + 1e-5f);
            s_sc[tid] = scv;
            s_off[tid] = (bias_prev[tid] - mean) * scv + beta[tid];
        }
        __syncthreads();
    }

    const float4* W4 = (const float4*)W;
    float4* Ws4 = (float4*)Ws;
#pragma unroll
    for (int i = tid; i < 1024; i += 256) Ws4[i] = W4[i];
#pragma unroll
    for (int i = tid; i < 1024; i += 256) {
        int r = i & 63, kq = i >> 6;
        int n = row0 + r;
        float4 v = make_float4(0.f, 0.f, 0.f, 0.f);
        if (n < N) {
            v = ((const float4*)src)[n * 16 + kq];
            if (BN) {
                int c = kq * 4;
                v.x = elu(v.x * s_sc[c + 0] + s_off[c + 0]);
                v.y = elu(v.y * s_sc[c + 1] + s_off[c + 1]);
                v.z = elu(v.z * s_sc[c + 2] + s_off[c + 2]);
                v.w = elu(v.w * s_sc[c + 3] + s_off[c + 3]);
            }
        }
        As[(kq * 4 + 0) * 64 + r] = v.x;
        As[(kq * 4 + 1) * 64 + r] = v.y;
        As[(kq * 4 + 2) * 64 + r] = v.z;
        As[(kq * 4 + 3) * 64 + r] = v.w;
    }
    __syncthreads();

    int c0 = (tid & 15) * 4;
    int r0 = (tid >> 4) * 4;
    float4 acc[4];
#pragma unroll
    for (int i = 0; i < 4; i++) acc[i] = make_float4(0.f, 0.f, 0.f, 0.f);

#pragma unroll
    for (int k = 0; k < 64; k++) {
        float4 av = *(const float4*)&As[k * 64 + r0];
        float4 wv = *(const float4*)&Ws[k * 64 + c0];
        float as_[4] = {av.x, av.y, av.z, av.w};
#pragma unroll
        for (int i = 0; i < 4; i++) {
            acc[i].x += as_[i] * wv.x;
            acc[i].y += as_[i] * wv.y;
            acc[i].z += as_[i] * wv.z;
            acc[i].w += as_[i] * wv.w;
        }
    }

    // store fp16 features + attention logit partials
    float a_s0 = a_src[c0], a_s1 = a_src[c0 + 1], a_s2 = a_src[c0 + 2], a_s3 = a_src[c0 + 3];
    float a_d0 = a_dst[c0], a_d1 = a_dst[c0 + 1], a_d2 = a_dst[c0 + 2], a_d3 = a_dst[c0 + 3];
    int cg = tid & 15;
#pragma unroll
    for (int i = 0; i < 4; i++) {
        int r = r0 + i;
        int n = row0 + r;
        if (n < N) {
            __half2 h01 = __floats2half2_rn(acc[i].x, acc[i].y);
            __half2 h23 = __floats2half2_rn(acc[i].z, acc[i].w);
            uint2 pack;
            pack.x = *(unsigned int*)&h01;
            pack.y = *(unsigned int*)&h23;
            *(uint2*)&g_xh16[n * 64 + c0] = pack;
        }
        shS[r][cg] = acc[i].x * a_s0 + acc[i].y * a_s1 + acc[i].z * a_s2 + acc[i].w * a_s3;
        shD[r][cg] = acc[i].x * a_d0 + acc[i].y * a_d1 + acc[i].z * a_d2 + acc[i].w * a_d3;
    }
    __syncthreads();

    if (tid < 128) {
        int row = tid >> 1, sel = tid & 1;
        int n = row0 + row;
        if (n < N) {
            const float* arr = sel ? &shD[row][0] : &shS[row][0];
            float* dsta = sel ? g_ald : g_als;
            if (H == 2) {
                float h0 = 0.f, h1 = 0.f;
#pragma unroll
                for (int j = 0; j < 8; j++) { h0 += arr[j]; h1 += arr[8 + j]; }
                dsta[2 * n] = h0;
                dsta[2 * n + 1] = h1;
            } else {
                float t = 0.f;
#pragma unroll
                for (int j = 0; j < 16; j++) t += arr[j];
                dsta[n] = t;
            }
        }
    }
}

// ---------------- gather: one warp per dst node; 32-edge chunks, shuffled weights ------------
template <int H>
__global__ void gather_kernel(const float* __restrict__ bias, float* __restrict__ bnpart, int N) {
    __shared__ float2 shS[8][32];
    __shared__ float2 shQ[8][32];
    int w = threadIdx.x >> 5, lane = threadIdx.x & 31;
    int d = blockIdx.x * 8 + w;
    bool valid = (d < N);
    float2 outv = make_float2(0.f, 0.f);

    if (valid) {
        float ald0, ald1, als0, als1;
        if (H == 2) {
            float2 adv = ((const float2*)g_ald)[d];
            float2 asv = ((const float2*)g_als)[d];
            ald0 = adv.x; ald1 = adv.y; als0 = asv.x; als1 = asv.y;
        } else {
            ald0 = ald1 = g_ald[d];
            als0 = als1 = g_als[d];
        }
        bool hi = (H == 2) && (lane >= 16);
        float ald_own = hi ? ald1 : ald0;
        float wself = __expf(lrelu((hi ? als1 : als0) + ald_own));

        float2 fv = __half22float2(((const __half2*)g_xh16)[d * 32 + lane]);
        float accx = wself * fv.x, accy = wself * fv.y, den = wself;

        int p = g_rowptr[d];
        int end = g_rowptr[d + 1];
        while (p < end) {
            int cnt = end - p;
            if (cnt > 32) cnt = 32;
            // lane-parallel load of indices + per-edge head weights (2 exp per edge per warp)
            int myi = (lane < cnt) ? __ldg(&g_ecsr[p + lane]) : 0;
            float w0 = 0.f, w1 = 0.f;
            if (lane < cnt) {
                if (H == 2) {
                    float2 av = __ldg(&((const float2*)g_als)[myi]);
                    w0 = __expf(lrelu(av.x + ald0));
                    w1 = __expf(lrelu(av.y + ald1));
                } else {
                    float av = __ldg(&g_als[myi]);
                    w0 = __expf(lrelu(av + ald0));
                }
            }
#pragma unroll 4
            for (int j = 0; j < cnt; j++) {
                int s = __shfl_sync(0xffffffffu, myi, j);
                float we;
                if (H == 2) {
                    float wj0 = __shfl_sync(0xffffffffu, w0, j);
                    float wj1 = __shfl_sync(0xffffffffu, w1, j);
                    we = hi ? wj1 : wj0;
                } else {
                    we = __shfl_sync(0xffffffffu, w0, j);
                }
                float2 nf = __half22float2(__ldg(&((const __half2*)g_xh16)[s * 32 + lane]));
                accx = fmaf(we, nf.x, accx);
                accy = fmaf(we, nf.y, accy);
                den += we;
            }
            p += 32;
        }
        float inv = 1.f / (den + 1e-16f);
        outv = make_float2(accx * inv, accy * inv);
        ((float2*)g_out)[d * 32 + lane] = outv;
    }

    // fused BN statistics: v = out + bias
    float2 bv = ((const float2*)bias)[lane];
    float vx = valid ? outv.x + bv.x : 0.f;
    float vy = valid ? outv.y + bv.y : 0.f;
    shS[w][lane] = make_float2(vx, vy);
    shQ[w][lane] = make_float2(vx * vx, vy * vy);
    __syncthreads();

    int c = threadIdx.x;
    if (c < 64) {
        int l = c >> 1, comp = c & 1;
        float s = 0.f, q = 0.f;
#pragma unroll
        for (int i = 0; i < 8; i++) {
            float2 sv = shS[i][l];
            float2 qv = shQ[i][l];
            s += comp ? sv.y : sv.x;
            q += comp ? qv.y : qv.x;
        }
        float* base = bnpart + (blockIdx.x & 31) * 128;
        atomicAdd(base + c, s);
        atomicAdd(base + 64 + c, q);
    }
}

__global__ void bn_finalize_kernel(const float* __restrict__ part, float* __restrict__ stat) {
    int c = threadIdx.x;  // 128
    float a = 0.f;
#pragma unroll
    for (int i = 0; i < 32; i++) a += part[i * 128 + c];
    stat[c] = a;
}

// ---------------- pooling with inline BN2+ELU: one block per graph; batch sorted ------------
__device__ __forceinline__ int lbound(const int* __restrict__ a, int n, int key) {
    int lo = 0, hi = n;
    while (lo < hi) {
        int mid = (lo + hi) >> 1;
        if (a[mid] < key) lo = mid + 1;
        else hi = mid;
    }
    return lo;
}

__global__ void pool_kernel(const int* __restrict__ batch,
                            const float* __restrict__ bias, const float* __restrict__ gamma,
                            const float* __restrict__ beta, const float* __restrict__ stat,
                            int N) {
    __shared__ float s_sc[64], s_off[64];
    __shared__ float shm[256], shs[256];
    int tid = threadIdx.x;
    if (tid < 64) {
        float invN = 1.f / (float)N;
        float mean = stat[tid] * invN;
        float var = stat[64 + tid] * invN - mean * mean;
        float scv = gamma[tid] * rsqrtf(var + 1e-5f);
        s_sc[tid] = scv;
        s_off[tid] = (bias[tid] - mean) * scv + beta[tid];
    }
    __syncthreads();

    int g = blockIdx.x;
    int c = tid & 63, rq = tid >> 6;
    int lo = lbound(batch, N, g);
    int hi = lbound(batch, N, g + 1);
    float sc = s_sc[c], off = s_off[c];
    float mx = -INFINITY, sm = 0.f;
    for (int n = lo + rq; n < hi; n += 4) {
        float v = elu(g_out[n * 64 + c] * sc + off);
        mx = fmaxf(mx, v);
        sm += v;
    }
    shm[tid] = mx;
    shs[tid] = sm;
    __syncthreads();
    if (rq == 0) {
        float m = fmaxf(fmaxf(shm[c], shm[64 + c]), fmaxf(shm[128 + c], shm[192 + c]));
        float s = shs[c] + shs[64 + c] + shs[128 + c] + shs[192 + c];
        int cnt = hi - lo;
        g_comb[g * 128 + c] = cnt > 0 ? m : 0.f;
        g_comb[g * 128 + 64 + c] = s / fmaxf((float)cnt, 1.f);
    }
}

// ---------------- output projection: [G,128] @ [128,128] + b ----------------
__global__ void outproj_kernel(const float* __restrict__ W, const float* __restrict__ b,
                               float* __restrict__ out) {
    int g = blockIdx.x;
    int c = threadIdx.x;  // 128
    __shared__ float row[128];
    row[c] = g_comb[g * 128 + c];
    __syncthreads();
    float acc = b[c];
#pragma unroll 16
    for (int k = 0; k < 128; k++) acc += row[k] * W[k * 128 + c];
    out[g * 128 + c] = acc;
}

// ---------------- host orchestration ----------------
extern "C" void kernel_launch(void* const* d_in, const int* in_sizes, int n_in,
                              void* d_out, int out_size) {
    const float* x     = (const float*)d_in[0];
    const int*   ei    = (const int*)d_in[1];
    const int*   batch = (const int*)d_in[2];
    const float* W_emb = (const float*)d_in[3];
    const float* b_emb = (const float*)d_in[4];
    const float* W1    = (const float*)d_in[5];
    const float* a1s   = (const float*)d_in[6];
    const float* a1d   = (const float*)d_in[7];
    const float* b1    = (const float*)d_in[8];
    const float* g1    = (const float*)d_in[9];
    const float* be1   = (const float*)d_in[10];
    const float* W2    = (const float*)d_in[11];
    const float* a2s   = (const float*)d_in[12];
    const float* a2d   = (const float*)d_in[13];
    const float* b2    = (const float*)d_in[14];
    const float* g2    = (const float*)d_in[15];
    const float* be2   = (const float*)d_in[16];
    const float* Wout  = (const float*)d_in[17];
    const float* bout  = (const float*)d_in[18];

    int N = in_sizes[0] / 4;
    int E = in_sizes[1] / 2;
    int G = out_size / 128;
    int NB = (N + 1023) / 1024;

    float* p_h0;   cudaGetSymbolAddress((void**)&p_h0, g_h0);
    float* p_out;  cudaGetSymbolAddress((void**)&p_out, g_out);
    float* p_bp1;  cudaGetSymbolAddress((void**)&p_bp1, g_bnpart1);
    float* p_bp2;  cudaGetSymbolAddress((void**)&p_bp2, g_bnpart2);
    float* p_st1;  cudaGetSymbolAddress((void**)&p_st1, g_bnstat1);
    float* p_st2;  cudaGetSymbolAddress((void**)&p_st2, g_bnstat2);

    // launches ordered so the 4th is gemm_fused (ncu captures launch #4)
    hist_zero_kernel<<<(N + 255) / 256, 256>>>(N);
    hist_kernel<<<(E + 255) / 256, 256>>>(ei, E);
    embed_kernel<<<(N * 64 + 255) / 256, 256>>>(x, W_emb, b_emb, N);
    gemm_fused_kernel<2, false><<<(N + 63) / 64, 256>>>(W1, a1s, a1d, p_h0,
                                                        nullptr, nullptr, nullptr, nullptr, N);
    scan_a_kernel<<<NB, 1024>>>(N);
    scan_b_kernel<<<1, 128>>>(NB, N);
    scan_c_kernel<<<NB, 1024>>>(N);
    scatter_kernel<<<(E + 255) / 256, 256>>>(ei, E);

    // layer 1 aggregation
    gather_kernel<2><<<(N + 7) / 8, 256>>>(b1, p_bp1, N);
    bn_finalize_kernel<<<1, 128>>>(p_bp1, p_st1);

    // layer 2 (BN1+ELU applied on load of g_out)
    gemm_fused_kernel<1, true><<<(N + 63) / 64, 256>>>(W2, a2s, a2d, p_out,
                                                       b1, g1, be1, p_st1, N);
    gather_kernel<1><<<(N + 7) / 8, 256>>>(b2, p_bp2, N);
    bn_finalize_kernel<<<1, 128>>>(p_bp2, p_st2);

    // pool (BN2+ELU applied on load) + projection
    pool_kernel<<<G, 256>>>(batch, b2, g2, be2, p_st2, N);
    outproj_kernel<<<G, 128>>>(Wout, bout, (float*)d_out);
}

// round 5
// speedup vs baseline: 2.5177x; 1.1672x over previous
#include <cuda_runtime.h>
#include <cuda_fp16.h>
#include <math.h>

// Problem-shape constants (padded)
#define NMAX 100352
#define GMAX 512
#define ECAP 3276800

// Scratch (device globals; allocation-free per harness rules)
__device__ __align__(128) float g_h0[NMAX * 64];      // embed output (fp32)
__device__ __align__(128) __half g_xh16[NMAX * 64];   // transformed features (fp16)
__device__ __align__(128) float g_out[NMAX * 64];     // raw aggregation output (pre-bias, pre-BN)
__device__ __align__(128) float g_als[NMAX * 2];
__device__ __align__(128) float g_ald[NMAX * 2];
__device__ __align__(128) float g_bnpart1[32 * 128];
__device__ __align__(128) float g_bnpart2[32 * 128];
__device__ __align__(128) float g_bnstat1[128];
__device__ __align__(128) float g_bnstat2[128];
__device__ __align__(128) float g_comb[GMAX * 128];
// CSR scratch
__device__ __align__(128) int g_cnt[NMAX];
__device__ __align__(128) int g_cursor[NMAX];
__device__ __align__(128) int g_rowptr[NMAX + 1];
__device__ __align__(128) int g_ecsr[ECAP];
__device__ __align__(128) int g_blocksum[128];

__device__ __forceinline__ float lrelu(float z) { return z > 0.f ? z : 0.2f * z; }
__device__ __forceinline__ float elu(float z) { return z > 0.f ? z : expm1f(z); }

// ---------------- CSR build ----------------
__global__ void hist_zero_kernel(int N) {
    int i = blockIdx.x * blockDim.x + threadIdx.x;
    if (i < 4096) { g_bnpart1[i] = 0.f; g_bnpart2[i] = 0.f; }
    if (i < N) g_cnt[i] = 0;
}

__global__ void hist_kernel(const int* __restrict__ ei, int E) {
    int e = blockIdx.x * blockDim.x + threadIdx.x;
    if (e >= E) return;
    atomicAdd(&g_cnt[__ldg(&ei[E + e])], 1);
}

__global__ void scan_a_kernel(int N) {
    __shared__ int sh[32];
    int i = blockIdx.x * 1024 + threadIdx.x;
    int lane = threadIdx.x & 31, wid = threadIdx.x >> 5;
    int v = (i < N) ? g_cnt[i] : 0;
#pragma unroll
    for (int o = 16; o; o >>= 1) v += __shfl_xor_sync(0xffffffffu, v, o);
    if (lane == 0) sh[wid] = v;
    __syncthreads();
    if (wid == 0) {
        int s = sh[lane];
#pragma unroll
        for (int o = 16; o; o >>= 1) s += __shfl_xor_sync(0xffffffffu, s, o);
        if (lane == 0) g_blocksum[blockIdx.x] = s;
    }
}

__global__ void scan_b_kernel(int NB, int N) {
    __shared__ int sh[128];
    int t = threadIdx.x;
    int v = (t < NB) ? g_blocksum[t] : 0;
    sh[t] = v;
    __syncthreads();
#pragma unroll
    for (int o = 1; o < 128; o <<= 1) {
        int a = (t >= o) ? sh[t - o] : 0;
        __syncthreads();
        sh[t] += a;
        __syncthreads();
    }
    if (t < NB) g_blocksum[t] = sh[t] - v;
    if (t == 127) g_rowptr[N] = sh[127];
}

__global__ void scan_c_kernel(int N) {
    __shared__ int warpsum[32];
    int i = blockIdx.x * 1024 + threadIdx.x;
    int lane = threadIdx.x & 31, wid = threadIdx.x >> 5;
    int v = (i < N) ? g_cnt[i] : 0;
    int x = v;
#pragma unroll
    for (int o = 1; o < 32; o <<= 1) {
        int y = __shfl_up_sync(0xffffffffu, x, o);
        if (lane >= o) x += y;
    }
    if (lane == 31) warpsum[wid] = x;
    __syncthreads();
    if (wid == 0) {
        int s = warpsum[lane];
#pragma unroll
        for (int o = 1; o < 32; o <<= 1) {
            int y = __shfl_up_sync(0xffffffffu, s, o);
            if (lane >= o) s += y;
        }
        warpsum[lane] = s;
    }
    __syncthreads();
    int woff = (wid > 0) ? warpsum[wid - 1] : 0;
    int excl = x - v + woff + g_blocksum[blockIdx.x];
    if (i < N) {
        g_rowptr[i] = excl;
        g_cursor[i] = excl;
    }
}

__global__ void scatter_kernel(const int* __restrict__ ei, int E) {
    int e = blockIdx.x * blockDim.x + threadIdx.x;
    if (e >= E) return;
    int s = __ldg(&ei[e]);
    int d = __ldg(&ei[E + e]);
    int pos = atomicAdd(&g_cursor[d], 1);
    g_ecsr[pos] = s;
}

// ---------------- embed: h0 = elu(x @ W_emb + b) ----------------
__global__ void embed_kernel(const float* __restrict__ x, const float* __restrict__ W,
                             const float* __restrict__ b, int N) {
    int t = blockIdx.x * blockDim.x + threadIdx.x;
    int n = t >> 6, c = t & 63;
    if (n >= N) return;
    float4 xv = ((const float4*)x)[n];
    float acc = b[c] + xv.x * W[c] + xv.y * W[64 + c] + xv.z * W[128 + c] + xv.w * W[192 + c];
    g_h0[n * 64 + c] = elu(acc);
}

// ---------------- fused GEMM: 128x64 tile, 8x4 per-thread register tile --------------------
// dynamic smem layout (floats): As[64*128] | Ws[64*64] | s_sc[64] | s_off[64]
template <int H, bool BN>
__global__ __launch_bounds__(256) void gemm_fused_kernel(
        const float* __restrict__ W,
        const float* __restrict__ a_src, const float* __restrict__ a_dst,
        const float* __restrict__ src,
        const float* __restrict__ bias_prev,
        const float* __restrict__ gamma, const float* __restrict__ beta,
        const float* __restrict__ stat, int N) {
    extern __shared__ float smem[];
    float* As = smem;                 // [k][r] 64 x 128
    float* Ws = smem + 8192;          // [k][c] 64 x 64
    float* s_sc = Ws + 4096;
    float* s_off = s_sc + 64;

    int row0 = blockIdx.x * 128;
    int tid = threadIdx.x;  // 256

    if (BN) {
        if (tid < 64) {
            float invN = 1.f / (float)N;
            float mean = stat[tid] * invN;
            float var = stat[64 + tid] * invN - mean * mean;
            float scv = gamma[tid] * rsqrtf(var + 1e-5f);
            s_sc[tid] = scv;
            s_off[tid] = (bias_prev[tid] - mean) * scv + beta[tid];
        }
        __syncthreads();
    }

    const float4* W4 = (const float4*)W;
    float4* Ws4 = (float4*)Ws;
#pragma unroll
    for (int i = tid; i < 1024; i += 256) Ws4[i] = W4[i];
#pragma unroll
    for (int i = tid; i < 2048; i += 256) {
        int r = i & 127, kq = i >> 7;
        int n = row0 + r;
        float4 v = make_float4(0.f, 0.f, 0.f, 0.f);
        if (n < N) {
            v = ((const float4*)src)[n * 16 + kq];
            if (BN) {
                int c = kq * 4;
                v.x = elu(v.x * s_sc[c + 0] + s_off[c + 0]);
                v.y = elu(v.y * s_sc[c + 1] + s_off[c + 1]);
                v.z = elu(v.z * s_sc[c + 2] + s_off[c + 2]);
                v.w = elu(v.w * s_sc[c + 3] + s_off[c + 3]);
            }
        }
        As[(kq * 4 + 0) * 128 + r] = v.x;
        As[(kq * 4 + 1) * 128 + r] = v.y;
        As[(kq * 4 + 2) * 128 + r] = v.z;
        As[(kq * 4 + 3) * 128 + r] = v.w;
    }
    __syncthreads();

    int cg = tid & 15;
    int c0 = cg * 4;
    int r0 = (tid >> 4) * 8;
    float acc[8][4];
#pragma unroll
    for (int i = 0; i < 8; i++)
#pragma unroll
        for (int j = 0; j < 4; j++) acc[i][j] = 0.f;

#pragma unroll 4
    for (int k = 0; k < 64; k++) {
        float4 wv = *(const float4*)&Ws[k * 64 + c0];
        float4 a0 = *(const float4*)&As[k * 128 + r0];
        float4 a1 = *(const float4*)&As[k * 128 + r0 + 4];
        float ar[8] = {a0.x, a0.y, a0.z, a0.w, a1.x, a1.y, a1.z, a1.w};
#pragma unroll
        for (int i = 0; i < 8; i++) {
            acc[i][0] = fmaf(ar[i], wv.x, acc[i][0]);
            acc[i][1] = fmaf(ar[i], wv.y, acc[i][1]);
            acc[i][2] = fmaf(ar[i], wv.z, acc[i][2]);
            acc[i][3] = fmaf(ar[i], wv.w, acc[i][3]);
        }
    }

    // store fp16 features; compute attention partials
    float a_s0 = a_src[c0], a_s1 = a_src[c0 + 1], a_s2 = a_src[c0 + 2], a_s3 = a_src[c0 + 3];
    float a_d0 = a_dst[c0], a_d1 = a_dst[c0 + 1], a_d2 = a_dst[c0 + 2], a_d3 = a_dst[c0 + 3];
    float pS[8], pD[8];
#pragma unroll
    for (int i = 0; i < 8; i++) {
        int n = row0 + r0 + i;
        if (n < N) {
            __half2 h01 = __floats2half2_rn(acc[i][0], acc[i][1]);
            __half2 h23 = __floats2half2_rn(acc[i][2], acc[i][3]);
            uint2 pack;
            pack.x = *(unsigned int*)&h01;
            pack.y = *(unsigned int*)&h23;
            *(uint2*)&g_xh16[n * 64 + c0] = pack;
        }
        pS[i] = acc[i][0] * a_s0 + acc[i][1] * a_s1 + acc[i][2] * a_s2 + acc[i][3] * a_s3;
        pD[i] = acc[i][0] * a_d0 + acc[i][1] * a_d1 + acc[i][2] * a_d2 + acc[i][3] * a_d3;
    }
    __syncthreads();  // done with As; reuse for partial sums
    float* shS = As;           // [128][16]
    float* shD = As + 2048;    // [128][16]
#pragma unroll
    for (int i = 0; i < 8; i++) {
        shS[(r0 + i) * 16 + cg] = pS[i];
        shD[(r0 + i) * 16 + cg] = pD[i];
    }
    __syncthreads();

    {
        int row = tid >> 1, sel = tid & 1;  // 128 rows x 2
        int n = row0 + row;
        if (n < N) {
            const float* arr = sel ? &shD[row * 16] : &shS[row * 16];
            float* dsta = sel ? g_ald : g_als;
            if (H == 2) {
                float h0 = 0.f, h1 = 0.f;
#pragma unroll
                for (int j = 0; j < 8; j++) { h0 += arr[j]; h1 += arr[8 + j]; }
                dsta[2 * n] = h0;
                dsta[2 * n + 1] = h1;
            } else {
                float t = 0.f;
#pragma unroll
                for (int j = 0; j < 16; j++) t += arr[j];
                dsta[n] = t;
            }
        }
    }
}

// ---------------- gather: warp/node; 32-edge chunks; 8-deep load pipeline -------------------
template <int H>
__global__ void gather_kernel(const float* __restrict__ bias, float* __restrict__ bnpart, int N) {
    __shared__ float2 shS[8][32];
    __shared__ float2 shQ[8][32];
    int w = threadIdx.x >> 5, lane = threadIdx.x & 31;
    int d = blockIdx.x * 8 + w;
    bool valid = (d < N);
    float2 outv = make_float2(0.f, 0.f);

    if (valid) {
        float ald0, ald1, als0, als1;
        if (H == 2) {
            float2 adv = ((const float2*)g_ald)[d];
            float2 asv = ((const float2*)g_als)[d];
            ald0 = adv.x; ald1 = adv.y; als0 = asv.x; als1 = asv.y;
        } else {
            ald0 = ald1 = g_ald[d];
            als0 = als1 = g_als[d];
        }
        bool hi = (H == 2) && (lane >= 16);
        float ald_own = hi ? ald1 : ald0;
        float wself = __expf(lrelu((hi ? als1 : als0) + ald_own));

        float2 fv = __half22float2(((const __half2*)g_xh16)[d * 32 + lane]);
        float accx = wself * fv.x, accy = wself * fv.y, den = wself;

        int p = g_rowptr[d];
        int end = g_rowptr[d + 1];
        while (p < end) {
            int cnt = end - p;
            if (cnt > 32) cnt = 32;
            int myi = 0;
            float w0 = 0.f, w1 = 0.f;
            if (lane < cnt) {
                myi = __ldg(&g_ecsr[p + lane]);
                if (H == 2) {
                    float2 av = __ldg(&((const float2*)g_als)[myi]);
                    w0 = __expf(lrelu(av.x + ald0));
                    w1 = __expf(lrelu(av.y + ald1));
                } else {
                    w0 = __expf(lrelu(__ldg(&g_als[myi]) + ald0));
                }
            }
            for (int b = 0; b < cnt; b += 8) {
                unsigned raw[8];
                float we[8];
#pragma unroll
                for (int j = 0; j < 8; j++) {
                    int s = __shfl_sync(0xffffffffu, myi, b + j);
                    raw[j] = __ldg((const unsigned*)&g_xh16[s * 64 + lane * 2]);
                }
#pragma unroll
                for (int j = 0; j < 8; j++) {
                    float wa = __shfl_sync(0xffffffffu, w0, b + j);
                    if (H == 2) {
                        float wb = __shfl_sync(0xffffffffu, w1, b + j);
                        we[j] = hi ? wb : wa;
                    } else {
                        we[j] = wa;
                    }
                }
#pragma unroll
                for (int j = 0; j < 8; j++) {
                    __half2 h = *(__half2*)&raw[j];
                    float2 nf = __half22float2(h);
                    accx = fmaf(we[j], nf.x, accx);
                    accy = fmaf(we[j], nf.y, accy);
                    den += we[j];
                }
            }
            p += 32;
        }
        float inv = 1.f / (den + 1e-16f);
        outv = make_float2(accx * inv, accy * inv);
        ((float2*)g_out)[d * 32 + lane] = outv;
    }

    // fused BN statistics: v = out + bias
    float2 bv = ((const float2*)bias)[lane];
    float vx = valid ? outv.x + bv.x : 0.f;
    float vy = valid ? outv.y + bv.y : 0.f;
    shS[w][lane] = make_float2(vx, vy);
    shQ[w][lane] = make_float2(vx * vx, vy * vy);
    __syncthreads();

    int c = threadIdx.x;
    if (c < 64) {
        int l = c >> 1, comp = c & 1;
        float s = 0.f, q = 0.f;
#pragma unroll
        for (int i = 0; i < 8; i++) {
            float2 sv = shS[i][l];
            float2 qv = shQ[i][l];
            s += comp ? sv.y : sv.x;
            q += comp ? qv.y : qv.x;
        }
        float* base = bnpart + (blockIdx.x & 31) * 128;
        atomicAdd(base + c, s);
        atomicAdd(base + 64 + c, q);
    }
}

__global__ void bn_finalize_kernel(const float* __restrict__ part, float* __restrict__ stat) {
    int c = threadIdx.x;  // 128
    float a = 0.f;
#pragma unroll
    for (int i = 0; i < 32; i++) a += part[i * 128 + c];
    stat[c] = a;
}

// ---------------- pooling with inline BN2+ELU ----------------
__device__ __forceinline__ int lbound(const int* __restrict__ a, int n, int key) {
    int lo = 0, hi = n;
    while (lo < hi) {
        int mid = (lo + hi) >> 1;
        if (a[mid] < key) lo = mid + 1;
        else hi = mid;
    }
    return lo;
}

__global__ void pool_kernel(const int* __restrict__ batch,
                            const float* __restrict__ bias, const float* __restrict__ gamma,
                            const float* __restrict__ beta, const float* __restrict__ stat,
                            int N) {
    __shared__ float s_sc[64], s_off[64];
    __shared__ float shm[256], shs[256];
    int tid = threadIdx.x;
    if (tid < 64) {
        float invN = 1.f / (float)N;
        float mean = stat[tid] * invN;
        float var = stat[64 + tid] * invN - mean * mean;
        float scv = gamma[tid] * rsqrtf(var + 1e-5f);
        s_sc[tid] = scv;
        s_off[tid] = (bias[tid] - mean) * scv + beta[tid];
    }
    __syncthreads();

    int g = blockIdx.x;
    int c = tid & 63, rq = tid >> 6;
    int lo = lbound(batch, N, g);
    int hi = lbound(batch, N, g + 1);
    float sc = s_sc[c], off = s_off[c];
    float mx = -INFINITY, sm = 0.f;
    for (int n = lo + rq; n < hi; n += 4) {
        float v = elu(g_out[n * 64 + c] * sc + off);
        mx = fmaxf(mx, v);
        sm += v;
    }
    shm[tid] = mx;
    shs[tid] = sm;
    __syncthreads();
    if (rq == 0) {
        float m = fmaxf(fmaxf(shm[c], shm[64 + c]), fmaxf(shm[128 + c], shm[192 + c]));
        float s = shs[c] + shs[64 + c] + shs[128 + c] + shs[192 + c];
        int cnt = hi - lo;
        g_comb[g * 128 + c] = cnt > 0 ? m : 0.f;
        g_comb[g * 128 + 64 + c] = s / fmaxf((float)cnt, 1.f);
    }
}

// ---------------- output projection: [G,128] @ [128,128] + b ----------------
__global__ void outproj_kernel(const float* __restrict__ W, const float* __restrict__ b,
                               float* __restrict__ out) {
    int g = blockIdx.x;
    int c = threadIdx.x;  // 128
    __shared__ float row[128];
    row[c] = g_comb[g * 128 + c];
    __syncthreads();
    float acc = b[c];
#pragma unroll 16
    for (int k = 0; k < 128; k++) acc += row[k] * W[k * 128 + c];
    out[g * 128 + c] = acc;
}

// ---------------- host orchestration ----------------
#define GEMM_SMEM (49664)

extern "C" void kernel_launch(void* const* d_in, const int* in_sizes, int n_in,
                              void* d_out, int out_size) {
    const float* x     = (const float*)d_in[0];
    const int*   ei    = (const int*)d_in[1];
    const int*   batch = (const int*)d_in[2];
    const float* W_emb = (const float*)d_in[3];
    const float* b_emb = (const float*)d_in[4];
    const float* W1    = (const float*)d_in[5];
    const float* a1s   = (const float*)d_in[6];
    const float* a1d   = (const float*)d_in[7];
    const float* b1    = (const float*)d_in[8];
    const float* g1    = (const float*)d_in[9];
    const float* be1   = (const float*)d_in[10];
    const float* W2    = (const float*)d_in[11];
    const float* a2s   = (const float*)d_in[12];
    const float* a2d   = (const float*)d_in[13];
    const float* b2    = (const float*)d_in[14];
    const float* g2    = (const float*)d_in[15];
    const float* be2   = (const float*)d_in[16];
    const float* Wout  = (const float*)d_in[17];
    const float* bout  = (const float*)d_in[18];

    int N = in_sizes[0] / 4;
    int E = in_sizes[1] / 2;
    int G = out_size / 128;
    int NB = (N + 1023) / 1024;

    float* p_h0;   cudaGetSymbolAddress((void**)&p_h0, g_h0);
    float* p_out;  cudaGetSymbolAddress((void**)&p_out, g_out);
    float* p_bp1;  cudaGetSymbolAddress((void**)&p_bp1, g_bnpart1);
    float* p_bp2;  cudaGetSymbolAddress((void**)&p_bp2, g_bnpart2);
    float* p_st1;  cudaGetSymbolAddress((void**)&p_st1, g_bnstat1);
    float* p_st2;  cudaGetSymbolAddress((void**)&p_st2, g_bnstat2);

    cudaFuncSetAttribute(gemm_fused_kernel<2, false>,
                         cudaFuncAttributeMaxDynamicSharedMemorySize, GEMM_SMEM);
    cudaFuncSetAttribute(gemm_fused_kernel<1, true>,
                         cudaFuncAttributeMaxDynamicSharedMemorySize, GEMM_SMEM);

    int gemm_grid = (N + 127) / 128;

    // launches ordered so the 4th is gemm_fused (ncu captures launch #4)
    hist_zero_kernel<<<(N + 255) / 256, 256>>>(N);
    hist_kernel<<<(E + 255) / 256, 256>>>(ei, E);
    embed_kernel<<<(N * 64 + 255) / 256, 256>>>(x, W_emb, b_emb, N);
    gemm_fused_kernel<2, false><<<gemm_grid, 256, GEMM_SMEM>>>(W1, a1s, a1d, p_h0,
                                                               nullptr, nullptr, nullptr, nullptr, N);
    scan_a_kernel<<<NB, 1024>>>(N);
    scan_b_kernel<<<1, 128>>>(NB, N);
    scan_c_kernel<<<NB, 1024>>>(N);
    scatter_kernel<<<(E + 255) / 256, 256>>>(ei, E);

    // layer 1 aggregation
    gather_kernel<2><<<(N + 7) / 8, 256>>>(b1, p_bp1, N);
    bn_finalize_kernel<<<1, 128>>>(p_bp1, p_st1);

    // layer 2 (BN1+ELU applied on load of g_out)
    gemm_fused_kernel<1, true><<<gemm_grid, 256, GEMM_SMEM>>>(W2, a2s, a2d, p_out,
                                                              b1, g1, be1, p_st1, N);
    gather_kernel<1><<<(N + 7) / 8, 256>>>(b2, p_bp2, N);
    bn_finalize_kernel<<<1, 128>>>(p_bp2, p_st2);

    // pool (BN2+ELU applied on load) + projection
    pool_kernel<<<G, 256>>>(batch, b2, g2, be2, p_st2, N);
    outproj_kernel<<<G, 128>>>(Wout, bout, (float*)d_out);
}